// round 1
// baseline (speedup 1.0000x reference)
#include <cuda_runtime.h>
#include <math.h>

#define N 8192
#define D 64
#define BM 64
#define SCALE 0.125f   // 1/sqrt(64)

// ---------------- scratch (static device globals; no allocation) ----------------
__device__ float g_Q[2][N * D];      // projected queries for x(0) / y(1)
__device__ float g_K[2][N * D];      // projected keys
__device__ float g_att[2][N * D];    // attention outputs
__device__ float g_norm[2][N];       // row squared norms of attention outputs

// ---------------- kernel 1: Q/K projection for both x and y ----------------
// grid = 2 * N/4 blocks, 256 threads. Each block: 4 rows, 64 cols, both W's.
__global__ __launch_bounds__(256) void proj_kernel(const float* __restrict__ x,
                                                   const float* __restrict__ y,
                                                   const float* __restrict__ Wq,
                                                   const float* __restrict__ Wk) {
    __shared__ float sWq[D * D];
    __shared__ float sWk[D * D];
    __shared__ float sIn[4][D];
    int tid = threadIdx.x;
    int b = blockIdx.x;
    int which = (b >= (N / 4)) ? 1 : 0;
    const float* in = which ? y : x;
    int row0 = (which ? b - N / 4 : b) * 4;

    for (int i = tid; i < D * D; i += 256) { sWq[i] = Wq[i]; sWk[i] = Wk[i]; }
    {
        int r = tid >> 6, c = tid & 63;
        sIn[r][c] = in[(row0 + r) * D + c];
    }
    __syncthreads();

    int r = tid >> 6, c = tid & 63;
    float aq = 0.f, ak = 0.f;
#pragma unroll
    for (int k = 0; k < D; k++) {
        float v = sIn[r][k];
        aq = fmaf(v, sWq[k * D + c], aq);
        ak = fmaf(v, sWk[k * D + c], ak);
    }
    g_Q[which][(row0 + r) * D + c] = aq;
    g_K[which][(row0 + r) * D + c] = ak;
}

// ---------------- kernel 2: flash attention (online softmax), fp32 ----------------
// grid = 2 * N/BM blocks (x then y), 256 threads (16x16), 4x4 micro-tile.
struct FlashSmem {
    float Qs[BM][D + 1];
    float Ks[BM][D + 1];
    float Vs[BM][D + 1];
    float Ps[BM][D + 1];
    float m[BM];
    float l[BM];
    float f[BM];
};

__global__ __launch_bounds__(256) void flash_kernel(const float* __restrict__ x,
                                                    const float* __restrict__ y) {
    extern __shared__ char smem_raw[];
    FlashSmem& sm = *reinterpret_cast<FlashSmem*>(smem_raw);

    int tid = threadIdx.x;
    int b = blockIdx.x;
    int which = (b >= (N / BM)) ? 1 : 0;
    int qb = which ? b - N / BM : b;
    const float* V = which ? y : x;
    const float* Q = g_Q[which];
    const float* K = g_K[which];
    int qrow0 = qb * BM;

    for (int i = tid; i < BM * D; i += 256)
        sm.Qs[i >> 6][i & 63] = Q[qrow0 * D + i];
    if (tid < BM) { sm.m[tid] = -INFINITY; sm.l[tid] = 0.f; }

    int ty = tid >> 4, tx = tid & 15;
    int r0 = ty * 4, c0 = tx * 4, d0 = tx * 4;
    float o[4][4] = {};

    for (int j0 = 0; j0 < N; j0 += BM) {
        __syncthreads();  // previous iteration's readers done; Qs/m/l ready (iter 0)
        for (int i = tid; i < BM * D; i += 256) {
            sm.Ks[i >> 6][i & 63] = K[j0 * D + i];
            sm.Vs[i >> 6][i & 63] = V[j0 * D + i];
        }
        __syncthreads();

        // S tile: 64x64, 4x4 per thread
        float s[4][4] = {};
#pragma unroll
        for (int k = 0; k < D; k++) {
            float qv[4], kv[4];
#pragma unroll
            for (int i = 0; i < 4; i++) qv[i] = sm.Qs[r0 + i][k];
#pragma unroll
            for (int j = 0; j < 4; j++) kv[j] = sm.Ks[c0 + j][k];
#pragma unroll
            for (int i = 0; i < 4; i++)
#pragma unroll
                for (int j = 0; j < 4; j++) s[i][j] = fmaf(qv[i], kv[j], s[i][j]);
        }
#pragma unroll
        for (int i = 0; i < 4; i++)
#pragma unroll
            for (int j = 0; j < 4; j++) sm.Ps[r0 + i][c0 + j] = s[i][j] * SCALE;
        __syncthreads();

        // online softmax per row (64 threads, one row each)
        if (tid < BM) {
            float mo = sm.m[tid];
            float mx = mo;
            for (int c = 0; c < BM; c++) mx = fmaxf(mx, sm.Ps[tid][c]);
            float fac = __expf(mo - mx);
            float sum = 0.f;
            for (int c = 0; c < BM; c++) {
                float p = __expf(sm.Ps[tid][c] - mx);
                sm.Ps[tid][c] = p;
                sum += p;
            }
            sm.l[tid] = sm.l[tid] * fac + sum;
            sm.m[tid] = mx;
            sm.f[tid] = fac;
        }
        __syncthreads();

        // rescale accumulators and add P @ V
        float fr[4];
#pragma unroll
        for (int i = 0; i < 4; i++) fr[i] = sm.f[r0 + i];
#pragma unroll
        for (int i = 0; i < 4; i++)
#pragma unroll
            for (int j = 0; j < 4; j++) o[i][j] *= fr[i];

        for (int c = 0; c < BM; c++) {
            float vv[4];
#pragma unroll
            for (int j = 0; j < 4; j++) vv[j] = sm.Vs[c][d0 + j];
#pragma unroll
            for (int i = 0; i < 4; i++) {
                float p = sm.Ps[r0 + i][c];
#pragma unroll
                for (int j = 0; j < 4; j++) o[i][j] = fmaf(p, vv[j], o[i][j]);
            }
        }
    }
    __syncthreads();

    float li[4];
#pragma unroll
    for (int i = 0; i < 4; i++) li[i] = 1.f / sm.l[r0 + i];
#pragma unroll
    for (int i = 0; i < 4; i++)
#pragma unroll
        for (int j = 0; j < 4; j++)
            g_att[which][(qrow0 + r0 + i) * D + d0 + j] = o[i][j] * li[i];
}

// ---------------- kernel 3: squared row norms of attention outputs ----------------
__global__ __launch_bounds__(256) void norm_kernel() {
    int i = blockIdx.x * 256 + threadIdx.x;  // 0 .. 2N-1
    int which = (i >= N) ? 1 : 0;
    int r = which ? i - N : i;
    float s = 0.f;
#pragma unroll
    for (int k = 0; k < D; k++) {
        float v = g_att[which][r * D + k];
        s = fmaf(v, v, s);
    }
    g_norm[which][r] = s;
}

// ---------------- kernel 4: pairwise RBF kernel matrix ----------------
// grid (N/64, N/64), 256 threads, 4x4 micro-tile, float4 stores.
__global__ __launch_bounds__(256) void pairwise_kernel(float* __restrict__ out) {
    __shared__ float Xs[64][D + 1];
    __shared__ float Ys[64][D + 1];
    __shared__ float xn[64];
    __shared__ float yn[64];
    int tid = threadIdx.x;
    int xrow0 = blockIdx.y * 64;
    int yrow0 = blockIdx.x * 64;

    for (int i = tid; i < 64 * D; i += 256) {
        Xs[i >> 6][i & 63] = g_att[0][xrow0 * D + i];
        Ys[i >> 6][i & 63] = g_att[1][yrow0 * D + i];
    }
    if (tid < 64) {
        xn[tid] = g_norm[0][xrow0 + tid];
        yn[tid] = g_norm[1][yrow0 + tid];
    }
    __syncthreads();

    int ty = tid >> 4, tx = tid & 15;
    int r0 = ty * 4, c0 = tx * 4;
    float acc[4][4] = {};
#pragma unroll
    for (int k = 0; k < D; k++) {
        float xv[4], yv[4];
#pragma unroll
        for (int i = 0; i < 4; i++) xv[i] = Xs[r0 + i][k];
#pragma unroll
        for (int j = 0; j < 4; j++) yv[j] = Ys[c0 + j][k];
#pragma unroll
        for (int i = 0; i < 4; i++)
#pragma unroll
            for (int j = 0; j < 4; j++) acc[i][j] = fmaf(xv[i], yv[j], acc[i][j]);
    }

#pragma unroll
    for (int i = 0; i < 4; i++) {
        float4 res;
        float a = xn[r0 + i];
        res.x = __expf(-(a + yn[c0 + 0] - 2.f * acc[i][0]));
        res.y = __expf(-(a + yn[c0 + 1] - 2.f * acc[i][1]));
        res.z = __expf(-(a + yn[c0 + 2] - 2.f * acc[i][2]));
        res.w = __expf(-(a + yn[c0 + 3] - 2.f * acc[i][3]));
        size_t row = (size_t)(xrow0 + r0 + i);
        *reinterpret_cast<float4*>(&out[row * N + yrow0 + c0]) = res;
    }
}

// ---------------- launch ----------------
extern "C" void kernel_launch(void* const* d_in, const int* in_sizes, int n_in,
                              void* d_out, int out_size) {
    const float* Wq = (const float*)d_in[0];  // rotation_params
    const float* Wk = (const float*)d_in[1];  // entangle_params
    const float* x  = (const float*)d_in[2];
    const float* y  = (const float*)d_in[3];
    float* out = (float*)d_out;

    proj_kernel<<<2 * N / 4, 256>>>(x, y, Wq, Wk);

    int flash_smem = (int)sizeof(FlashSmem);
    cudaFuncSetAttribute(flash_kernel, cudaFuncAttributeMaxDynamicSharedMemorySize,
                         flash_smem);
    flash_kernel<<<2 * N / BM, 256, flash_smem>>>(x, y);

    norm_kernel<<<2 * N / 256, 256>>>();

    dim3 grid(N / 64, N / 64);
    pairwise_kernel<<<grid, 256>>>(out);
}